// round 10
// baseline (speedup 1.0000x reference)
#include <cuda_runtime.h>

// SpectralConv2d via DHT — 3-kernel pipeline tuned for occupancy/overlap.
// (R9 with the K1 bottom-block row-map fix: rl+192, not rl+160.)
//
//   A[gr][y]  = sum_k x[b,i,row,k] * cas(2pi*k*y/256),  gr=(b,i,rl), y<32
//   r[o][y]   = sum_i A[i][y] * w_blk[i,o,x,y]
//   out[o][k] = sum_y r[o][y] * M[y][k]   for the 64 live rows; 0 elsewhere
//   M[y][k]   = ( sum_j cas(2pi*y*j/32) * cas(2pi*j*k/256) ) * 2^-42

#define S 256

__device__ float4 g_B4[256 * 8];        // [k][q] = cas table, 4 y per entry
__device__ float  g_M[32 * 256];        // folded trailing transforms
__device__ float  g_A[2 * 16384 * 32];  // k-split partial DHT results (4 MB)

// ---------------------------------------------------------------------------
// K0: build g_B4 and the folded 32x256 matrix M.
// ---------------------------------------------------------------------------
__global__ void k0_tables() {
    __shared__ float c256[256];
    __shared__ float c32[32];
    const float TWO_PI = 6.283185307179586476925286766559f;
    int t = threadIdx.x;
    {
        float s, c;
        sincosf((TWO_PI / 256.0f) * (float)t, &s, &c);
        c256[t] = c + s;
        if (t < 32) {
            float s2, c2;
            sincosf((TWO_PI / 32.0f) * (float)t, &s2, &c2);
            c32[t] = c2 + s2;
        }
    }
    __syncthreads();
    int gid = blockIdx.x * 256 + t;          // 0..8191
    {   // M[y][k]
        int y = gid >> 8, k = gid & 255;
        float acc = 0.0f;
#pragma unroll
        for (int j = 0; j < 32; j++)
            acc += c32[(y * j) & 31] * c256[(j * k) & 255];
        g_M[gid] = acc * 0x1p-42f;
    }
    if (gid < 2048) {                        // g_B4[k][q], y = 4q..4q+3
        int k = gid >> 3, q = gid & 7;
        float4 v;
        v.x = c256[(k * (4 * q + 0)) & 255];
        v.y = c256[(k * (4 * q + 1)) & 255];
        v.z = c256[(k * (4 * q + 2)) & 255];
        v.w = c256[(k * (4 * q + 3)) & 255];
        g_B4[gid] = v;
    }
}

// ---------------------------------------------------------------------------
// K1: corner DHT as a tall GEMM (16384 live rows x 256k x 32y), k-split by 2.
// Grid 256 x 256 thr. Block (gblk, kh): rows gblk*128..+127, k-half kh.
// Thread: rows (rp, rp+64) x y-oct (8*yo). Also zeroes 26 MB of dead output.
// ---------------------------------------------------------------------------
__global__ __launch_bounds__(256) void k1_dht(const float* __restrict__ xin,
                                              float* __restrict__ out) {
    __shared__ float xs[128 * 33];           // [r][kk] pitch 33, 16.9 KB

    int t    = threadIdx.x;
    int bid  = blockIdx.x;
    int gblk = bid >> 1, kh = bid & 1;
    int gr0  = gblk * 128;
    int b    = gr0 >> 11;
    int i0   = (gr0 >> 6) & 31;

    // ---- zero-fill share: first 1,638,400 dead float4s ----
    {
        float4* o4 = (float4*)out;
        int tg = bid * 256 + t;
#pragma unroll
        for (int c = 0; c < 25; c++) {
            int D = c * 65536 + tg;
            int img = D / 12288;
            int j = D - img * 12288;
            o4[img * 16384 + 2048 + j] = make_float4(0.f, 0.f, 0.f, 0.f);
        }
    }

    int rp = t & 63, yo = t >> 6;            // rows rp, rp+64; y = 8yo..8yo+7
    float4 a00 = make_float4(0,0,0,0), a01 = a00, a10 = a00, a11 = a00;

    const float4* x4 = (const float4*)xin;
#pragma unroll 1
    for (int tt = 0; tt < 4; tt++) {
        int kt = kh * 4 + tt;                // k-tile of 32: k = 32kt..
        __syncthreads();
        // stage x tile [128 rows][32 k] (coalesced, 4 float4 per thread)
#pragma unroll
        for (int n = t; n < 1024; n += 256) {
            int r = n >> 3, q = n & 7;
            int i = i0 + (r >> 6);
            int rl = r & 63;
            int grow = rl < 32 ? rl : rl + 192;      // rows 0..31 / 224..255
            float4 v = x4[(size_t)((b * 32 + i) * 256 + grow) * 64 + kt * 8 + q];
            int base = r * 33 + 4 * q;
            xs[base + 0] = v.x; xs[base + 1] = v.y;
            xs[base + 2] = v.z; xs[base + 3] = v.w;
        }
        __syncthreads();
#pragma unroll 8
        for (int kk = 0; kk < 32; kk++) {
            int k = kt * 32 + kk;
            float4 b0 = __ldg(&g_B4[k * 8 + 2 * yo]);      // warp-uniform
            float4 b1 = __ldg(&g_B4[k * 8 + 2 * yo + 1]);  // warp-uniform
            float xa = xs[rp * 33 + kk];                   // conflict-free
            float xb = xs[(rp + 64) * 33 + kk];
            a00.x += xa*b0.x; a00.y += xa*b0.y; a00.z += xa*b0.z; a00.w += xa*b0.w;
            a01.x += xa*b1.x; a01.y += xa*b1.y; a01.z += xa*b1.z; a01.w += xa*b1.w;
            a10.x += xb*b0.x; a10.y += xb*b0.y; a10.z += xb*b0.z; a10.w += xb*b0.w;
            a11.x += xb*b1.x; a11.y += xb*b1.y; a11.z += xb*b1.z; a11.w += xb*b1.w;
        }
    }
    float4* A4 = (float4*)g_A + (size_t)kh * 131072;
    A4[(gr0 + rp) * 8 + 2 * yo]          = a00;
    A4[(gr0 + rp) * 8 + 2 * yo + 1]      = a01;
    A4[(gr0 + rp + 64) * 8 + 2 * yo]     = a10;
    A4[(gr0 + rp + 64) * 8 + 2 * yo + 1] = a11;
}

// ---------------------------------------------------------------------------
// K2: channel mix + folded trailing transforms. Grid 512 x 128 thr (lean
// blocks -> ~8 resident/SM). Block = (b, blk, x). Also zeroes 24 MB dead rows.
// ---------------------------------------------------------------------------
__global__ __launch_bounds__(128) void k2_mix(const float* __restrict__ w1,
                                              const float* __restrict__ w2,
                                              float* __restrict__ out) {
    __shared__ float As[32 * 36];            // [i][y] pitch 36
    __shared__ float rst[32 * 36];           // [y][o] pitch 36

    int t   = threadIdx.x;
    int bid = blockIdx.x;
    int x   = bid & 31;
    int blk = (bid >> 5) & 1;
    int b   = bid >> 6;
    int row = blk ? (224 + x) : x;
    const float* w = blk ? w2 : w1;

    // ---- zero-fill share: remaining 1,507,328 dead float4s ----
    {
        float4* o4 = (float4*)out;
        int tg = bid * 128 + t;
#pragma unroll
        for (int c = 0; c < 23; c++) {
            int D = 1638400 + c * 65536 + tg;
            int img = D / 12288;
            int j = D - img * 12288;
            o4[img * 16384 + 2048 + j] = make_float4(0.f, 0.f, 0.f, 0.f);
        }
    }

    // ---- load A slice (sum the two k-half partials), coalesced ----
    {
        int base = (b * 2048 + blk * 32 + x) * 32;   // + i*2048 floats
#pragma unroll
        for (int n = t; n < 1024; n += 128) {
            int i = n >> 5, y = n & 31;
            int idx = base + i * 2048 + y;
            As[i * 36 + y] = g_A[idx] + g_A[524288 + idx];
        }
    }
    __syncthreads();

    // ---- phase 1: r[o][y] = sum_i A[i][y] * w[i][o][x][y] ----
    {
        int o = t >> 2, y8 = (t & 3) * 8;
        float4 A0 = make_float4(0,0,0,0), A1 = A0;
        const float4* wp4 = (const float4*)(w + (size_t)o * 1024 + x * 32 + y8);
#pragma unroll 8
        for (int i = 0; i < 32; i++) {
            float4 wv0 = __ldg(wp4 + (size_t)i * 8192);
            float4 wv1 = __ldg(wp4 + (size_t)i * 8192 + 1);
            float4 av0 = *(const float4*)&As[i * 36 + y8];
            float4 av1 = *(const float4*)&As[i * 36 + y8 + 4];
            A0.x += av0.x * wv0.x; A0.y += av0.y * wv0.y;
            A0.z += av0.z * wv0.z; A0.w += av0.w * wv0.w;
            A1.x += av1.x * wv1.x; A1.y += av1.y * wv1.y;
            A1.z += av1.z * wv1.z; A1.w += av1.w * wv1.w;
        }
        rst[(y8 + 0) * 36 + o] = A0.x;
        rst[(y8 + 1) * 36 + o] = A0.y;
        rst[(y8 + 2) * 36 + o] = A0.z;
        rst[(y8 + 3) * 36 + o] = A0.w;
        rst[(y8 + 4) * 36 + o] = A1.x;
        rst[(y8 + 5) * 36 + o] = A1.y;
        rst[(y8 + 6) * 36 + o] = A1.z;
        rst[(y8 + 7) * 36 + o] = A1.w;
    }
    __syncthreads();

    // ---- phase 2: out[o][k] = sum_y rst[y][o] * M[y][k] ----
    {
        int lane = t & 31, wp = t >> 5;
        int ob = wp * 8;                     // warp -> o-oct
#pragma unroll 1
        for (int kh = 0; kh < 2; kh++) {     // k-half: k = kh*128 + 4*lane
            float4 a[8];
#pragma unroll
            for (int j = 0; j < 8; j++) a[j] = make_float4(0,0,0,0);
            const float4* Mp = (const float4*)(g_M + kh * 128) + lane;
#pragma unroll 8
            for (int yy = 0; yy < 32; yy++) {
                float4 mv = __ldg(Mp + yy * 64);               // coalesced
                float4 ra = *(const float4*)&rst[yy * 36 + ob];     // uniform
                float4 rb = *(const float4*)&rst[yy * 36 + ob + 4]; // uniform
                a[0].x += ra.x*mv.x; a[0].y += ra.x*mv.y; a[0].z += ra.x*mv.z; a[0].w += ra.x*mv.w;
                a[1].x += ra.y*mv.x; a[1].y += ra.y*mv.y; a[1].z += ra.y*mv.z; a[1].w += ra.y*mv.w;
                a[2].x += ra.z*mv.x; a[2].y += ra.z*mv.y; a[2].z += ra.z*mv.z; a[2].w += ra.z*mv.w;
                a[3].x += ra.w*mv.x; a[3].y += ra.w*mv.y; a[3].z += ra.w*mv.z; a[3].w += ra.w*mv.w;
                a[4].x += rb.x*mv.x; a[4].y += rb.x*mv.y; a[4].z += rb.x*mv.z; a[4].w += rb.x*mv.w;
                a[5].x += rb.y*mv.x; a[5].y += rb.y*mv.y; a[5].z += rb.y*mv.z; a[5].w += rb.y*mv.w;
                a[6].x += rb.z*mv.x; a[6].y += rb.z*mv.y; a[6].z += rb.z*mv.z; a[6].w += rb.z*mv.w;
                a[7].x += rb.w*mv.x; a[7].y += rb.w*mv.y; a[7].z += rb.w*mv.z; a[7].w += rb.w*mv.w;
            }
            float* op = out + ((size_t)(b * 32 + ob) * S + row) * S + kh * 128 + 4 * lane;
#pragma unroll
            for (int j = 0; j < 8; j++)
                *(float4*)(op + (size_t)j * (S * S)) = a[j];
        }
    }
}

// ---------------------------------------------------------------------------
extern "C" void kernel_launch(void* const* d_in, const int* in_sizes, int n_in,
                              void* d_out, int out_size) {
    const float* x  = (const float*)d_in[0];
    const float* w1 = (const float*)d_in[1];
    const float* w2 = (const float*)d_in[2];
    float* out = (float*)d_out;

    k0_tables<<<32, 256>>>();
    k1_dht<<<256, 256>>>(x, out);
    k2_mix<<<512, 128>>>(w1, w2, out);
}

// round 11
// speedup vs baseline: 1.3195x; 1.3195x over previous
#include <cuda_runtime.h>

// SpectralConv2d via DHT — single fused kernel; all transform tables are
// computed at COMPILE TIME (constexpr double Taylor series), so there is no
// table-builder kernel on the critical path.
//
//   A[i][y]   = sum_k x[b,i,row,k] * B[k][y],   B[k][y]=cas(2pi*k*y/256), y<32
//   r[o][y]   = sum_i A[i][y] * w_blk[i,o,x,y]
//   out[o][k] = sum_y r[o][y] * M[y][k]   for the 64 live rows; 0 elsewhere
//   M[y][k]   = ( sum_j cas(2pi*y*j/32) * cas(2pi*j*k/256) ) * 2^-42

#define NB 8
#define S  256

// ---------------------------------------------------------------------------
// Compile-time trig tables (double precision, exact 2pi*m/256 reduction).
// ---------------------------------------------------------------------------
constexpr double CPI = 3.14159265358979323846264338327950288;

constexpr double tpoly_cos(double x) {   // |x| <= pi/2
    double x2 = x * x, term = 1.0, sum = 1.0;
    for (int n = 1; n <= 12; n++) { term *= -x2 / ((2.0*n - 1) * (2.0*n)); sum += term; }
    return sum;
}
constexpr double tpoly_sin(double x) {   // |x| <= pi/2
    double x2 = x * x, term = x, sum = x;
    for (int n = 1; n <= 12; n++) { term *= -x2 / ((2.0*n) * (2.0*n + 1)); sum += term; }
    return sum;
}
constexpr double cos256(int m) {         // cos(2*pi*m/256)
    m &= 255; int s = 1;
    if (m > 128) m = 256 - m;
    if (m > 64) { m = 128 - m; s = -1; }
    return s * tpoly_cos((CPI * m) / 128.0);
}
constexpr double sin256(int m) {         // sin(2*pi*m/256)
    m &= 255; int s = 1;
    if (m > 128) { m = 256 - m; s = -1; }
    if (m > 64) { m = 128 - m; }
    return s * tpoly_sin((CPI * m) / 128.0);
}

struct alignas(16) Tables {
    float B[2048][4];   // [kc*32+y] = {cas(4kc*y), cas((4kc+1)y), .., cas((4kc+3)y)}
    float M[8192];      // [y*256+k] folded trailing transforms * 2^-42
};

constexpr Tables make_tables() {
    Tables t{};
    double c256[256] = {}, s256[256] = {};
    for (int m = 0; m < 256; m++) { c256[m] = cos256(m); s256[m] = sin256(m); }
    for (int kc = 0; kc < 64; kc++)
        for (int y = 0; y < 32; y++)
            for (int c = 0; c < 4; c++) {
                int m = ((4 * kc + c) * y) & 255;
                t.B[kc * 32 + y][c] = (float)(c256[m] + s256[m]);
            }
    for (int y = 0; y < 32; y++)
        for (int k = 0; k < 256; k++) {
            double acc = 0.0;
            for (int j = 0; j < 32; j++) {
                int m32 = 8 * ((y * j) & 31);
                int m   = (j * k) & 255;
                acc += (c256[m32] + s256[m32]) * (c256[m] + s256[m]);
            }
            t.M[y * 256 + k] = (float)(acc * 0x1p-42);
        }
    return t;
}

__device__ const Tables g_T = make_tables();

// ---------------------------------------------------------------------------
// F: fused DHT + channel mix + folded inverse transforms + zero-fill.
// One block per (b, blk, x); 256 threads. Warp-private x staging: warp ig
// loads exactly the 4 channel rows its phase A consumes -> __syncwarp only.
// ---------------------------------------------------------------------------
__global__ __launch_bounds__(256) void f_fused(const float* __restrict__ xin,
                                               const float* __restrict__ w1,
                                               const float* __restrict__ w2,
                                               float* __restrict__ out) {
    __shared__ float4 xs4[32 * 64];   // [i][kc]  natural layout, 32 KB
    __shared__ float  As[32 * 36];    // [i][y]   pitch 36 (float4-aligned)
    __shared__ float  rst[32 * 33];   // [y][o]   pitch 33 (conflict-free writes)

    int t    = threadIdx.x;
    int lane = t & 31, ig = t >> 5;
    int bid  = blockIdx.x;
    int x    = bid & 31;
    int blk  = (bid >> 5) & 1;
    int b    = bid >> 6;
    int row  = blk ? (224 + x) : x;
    const float* w = blk ? w2 : w1;

    // ---- warp-private x staging: warp ig loads rows 4ig..4ig+3 ----
    {
        const float4* x4 = (const float4*)xin;
#pragma unroll
        for (int j = 0; j < 4; j++) {
            int i = 4 * ig + j;
            size_t b4 = ((size_t)(b * 32 + i) * S + row) * 64;
            xs4[i * 64 + lane]      = x4[b4 + lane];
            xs4[i * 64 + 32 + lane] = x4[b4 + 32 + lane];
        }
        __syncwarp();
    }

    // ---- phase A: corner DHT. thread (y=lane, ig=warp) -> A[4ig..4ig+3][y] ----
    {
        int y = lane;
        float a0 = 0.f, a1 = 0.f, a2 = 0.f, a3 = 0.f;
        const float4* Bt = (const float4*)g_T.B + y;
        const float4* xr = xs4 + 4 * ig * 64;
#pragma unroll 8
        for (int kc = 0; kc < 64; kc++) {
            float4 bv = __ldg(&Bt[kc * 32]);         // coalesced across lanes
            float4 x0 = xr[kc];                      // i = 4ig   (broadcast)
            float4 x1 = xr[kc + 64];                 // i = 4ig+1
            float4 x2 = xr[kc + 128];
            float4 x3 = xr[kc + 192];
            a0 += x0.x*bv.x + x0.y*bv.y + x0.z*bv.z + x0.w*bv.w;
            a1 += x1.x*bv.x + x1.y*bv.y + x1.z*bv.z + x1.w*bv.w;
            a2 += x2.x*bv.x + x2.y*bv.y + x2.z*bv.z + x2.w*bv.w;
            a3 += x3.x*bv.x + x3.y*bv.y + x3.z*bv.z + x3.w*bv.w;
        }
        As[(4 * ig + 0) * 36 + y] = a0;
        As[(4 * ig + 1) * 36 + y] = a1;
        As[(4 * ig + 2) * 36 + y] = a2;
        As[(4 * ig + 3) * 36 + y] = a3;
    }

    // ---- zero-fill dead rows [32,224): stores drain during barrier wait ----
    {
        int img = bid >> 1, half = bid & 1;
        float4* o4 = (float4*)out + (size_t)img * 16384 + 2048 + half * 6144 + t;
#pragma unroll
        for (int j = 0; j < 24; j++) o4[j * 256] = make_float4(0.f, 0.f, 0.f, 0.f);
    }
    __syncthreads();

    // ---- phase 1: channel mix. thread (yg = t&7, o = t>>3) ----
    {
        int yg = t & 7, o = t >> 3;
        float4 acc = make_float4(0.f, 0.f, 0.f, 0.f);
        const float4* wp = (const float4*)(w + (size_t)o * 1024 + x * 32 + 4 * yg);
        const float4* ap = (const float4*)(As + 4 * yg);
#pragma unroll 8
        for (int i = 0; i < 32; i++) {
            float4 wv = __ldg(&wp[(size_t)i * 8192]);  // 32768 floats / 4
            float4 av = ap[i * 9];                     // 36 floats / 4
            acc.x += av.x * wv.x;
            acc.y += av.y * wv.y;
            acc.z += av.z * wv.z;
            acc.w += av.w * wv.w;
        }
        rst[(4 * yg + 0) * 33 + o] = acc.x;
        rst[(4 * yg + 1) * 33 + o] = acc.y;
        rst[(4 * yg + 2) * 33 + o] = acc.z;
        rst[(4 * yg + 3) * 33 + o] = acc.w;
    }
    __syncthreads();

    // ---- phase 2: trailing transforms. thread (k4 = (t&63)*4, ob = (t>>6)*8) ----
    {
        int k4 = (t & 63) * 4;
        int ob = (t >> 6) * 8;
        float4 acc[8];
#pragma unroll
        for (int j = 0; j < 8; j++) acc[j] = make_float4(0.f, 0.f, 0.f, 0.f);
        const float4* Mp = (const float4*)g_T.M + (k4 >> 2);
#pragma unroll 4
        for (int yy = 0; yy < 32; yy++) {
            float4 mv = __ldg(&Mp[yy * 64]);         // coalesced, L1-resident
            const float* rp = rst + yy * 33 + ob;
#pragma unroll
            for (int j = 0; j < 8; j++) {
                float rv = rp[j];                    // warp-uniform broadcast
                acc[j].x += rv * mv.x;
                acc[j].y += rv * mv.y;
                acc[j].z += rv * mv.z;
                acc[j].w += rv * mv.w;
            }
        }
        float* op = out + (((size_t)(b * 32 + ob)) * S + row) * S + k4;
#pragma unroll
        for (int j = 0; j < 8; j++)
            *(float4*)(op + (size_t)j * (S * S)) = acc[j];
    }
}

// ---------------------------------------------------------------------------
extern "C" void kernel_launch(void* const* d_in, const int* in_sizes, int n_in,
                              void* d_out, int out_size) {
    const float* x  = (const float*)d_in[0];
    const float* w1 = (const float*)d_in[1];
    const float* w2 = (const float*)d_in[2];
    float* out = (float*)d_out;

    f_fused<<<NB * 2 * 32, 256>>>(x, w1, w2, out);
}

// round 12
// speedup vs baseline: 1.5552x; 1.1786x over previous
#include <cuda_runtime.h>
#include <cstdint>

// SpectralConv2d via DHT — fused kernel; phases A and 2 run on tensor cores
// (mma.sync m16n8k8 tf32, 3xTF32 hi/lo for fp32-grade accuracy). Constant
// B-operand fragments are packed at compile time.
//
//   A[i][y]   = sum_k x[b,i,row,k] * B[k][y],  B[k][y]=cas(2pi*k*y/256), y<32
//   r[o][y]   = sum_i A[i][y] * w_blk[i,o,x,y]
//   out[o][k] = sum_y r[o][y] * Mm[y][k]  for the 64 live rows; 0 elsewhere
//   Mm[y][k]  = ( sum_j cas(2pi*y*j/32) * cas(2pi*j*k/256) ) * 2^-42

#define NB 8
#define S  256

// ---------------------------------------------------------------------------
// Compile-time trig + tf32 fragment tables.
// ---------------------------------------------------------------------------
constexpr double CPI = 3.14159265358979323846264338327950288;

constexpr double tpoly_cos(double x) {
    double x2 = x * x, term = 1.0, sum = 1.0;
    for (int n = 1; n <= 12; n++) { term *= -x2 / ((2.0*n - 1) * (2.0*n)); sum += term; }
    return sum;
}
constexpr double tpoly_sin(double x) {
    double x2 = x * x, term = x, sum = x;
    for (int n = 1; n <= 12; n++) { term *= -x2 / ((2.0*n) * (2.0*n + 1)); sum += term; }
    return sum;
}
constexpr double cos256(int m) {
    m &= 255; int s = 1;
    if (m > 128) m = 256 - m;
    if (m > 64) { m = 128 - m; s = -1; }
    return s * tpoly_cos((CPI * m) / 128.0);
}
constexpr double sin256(int m) {
    m &= 255; int s = 1;
    if (m > 128) { m = 256 - m; s = -1; }
    if (m > 64) { m = 128 - m; }
    return s * tpoly_sin((CPI * m) / 128.0);
}
constexpr double casd(int m) { return cos256(m) + sin256(m); }

constexpr float tf_hi(double v) {            // truncate to tf32 (lo absorbs rest)
    float f = (float)v;
    unsigned u = __builtin_bit_cast(unsigned, f);
    u &= 0xFFFFE000u;
    return __builtin_bit_cast(float, u);
}
constexpr float tf_lo(double v) {
    float h = tf_hi(v);
    float l = (float)(v - (double)h);
    unsigned u = __builtin_bit_cast(unsigned, l);
    u &= 0xFFFFE000u;
    return __builtin_bit_cast(float, u);
}

struct alignas(16) F4 { float x, y, z, w; };

// PA[(ks*4+nt)*32+lane]: B-frag for phase A  (B is 256k x 32y, K-dim = k)
//   lane: c = lane&3 (k within 8), g = lane>>2 (n within 8)
//   {b0_hi, b1_hi, b0_lo, b1_lo}, b0 = B[8ks+c][8nt+g], b1 = B[8ks+c+4][..]
// PM[(ks*32+nt)*32+lane]: same packing for Mm (32y x 256k, K-dim = y)
struct Tables {
    F4 PA[32 * 4 * 32];
    F4 PM[4 * 32 * 32];
};

constexpr Tables make_tables() {
    Tables t{};
    double cas[256] = {};
    for (int m = 0; m < 256; m++) cas[m] = casd(m);
    // phase A fragments: B[k][y] = cas(k*y mod 256)
    for (int ks = 0; ks < 32; ks++)
        for (int nt = 0; nt < 4; nt++)
            for (int lane = 0; lane < 32; lane++) {
                int c = lane & 3, g = lane >> 2;
                int k0 = 8 * ks + c, k1 = k0 + 4, y = 8 * nt + g;
                double b0 = cas[(k0 * y) & 255], b1 = cas[(k1 * y) & 255];
                t.PA[(ks * 4 + nt) * 32 + lane] =
                    F4{tf_hi(b0), tf_hi(b1), tf_lo(b0), tf_lo(b1)};
            }
    // Mm[y][k]
    static_assert(sizeof(F4) == 16, "");
    {
        for (int ks = 0; ks < 4; ks++)
            for (int nt = 0; nt < 32; nt++)
                for (int lane = 0; lane < 32; lane++) {
                    int c = lane & 3, g = lane >> 2;
                    int y0 = 8 * ks + c, y1 = y0 + 4, k = 8 * nt + g;
                    double m0 = 0.0, m1 = 0.0;
                    for (int j = 0; j < 32; j++) {
                        double cj = cas[(j * k) & 255];
                        m0 += cas[(8 * ((y0 * j) & 31)) & 255] * cj;
                        m1 += cas[(8 * ((y1 * j) & 31)) & 255] * cj;
                    }
                    m0 *= 0x1p-42; m1 *= 0x1p-42;
                    t.PM[(ks * 32 + nt) * 32 + lane] =
                        F4{tf_hi(m0), tf_hi(m1), tf_lo(m0), tf_lo(m1)};
                }
    }
    return t;
}

__device__ const Tables g_T = make_tables();

// ---------------------------------------------------------------------------
// mma helpers
// ---------------------------------------------------------------------------
__device__ __forceinline__ uint32_t cvt_tf32(float f) {
    uint32_t r; asm("cvt.rna.tf32.f32 %0, %1;" : "=r"(r) : "f"(f)); return r;
}
#define MMA_TF32(d0,d1,d2,d3,a0,a1,a2,a3,b0,b1)                             \
    asm("mma.sync.aligned.m16n8k8.row.col.f32.tf32.tf32.f32 "               \
        "{%0,%1,%2,%3}, {%4,%5,%6,%7}, {%8,%9}, {%0,%1,%2,%3};"             \
        : "+f"(d0), "+f"(d1), "+f"(d2), "+f"(d3)                            \
        : "r"(a0), "r"(a1), "r"(a2), "r"(a3), "r"(b0), "r"(b1))

// ---------------------------------------------------------------------------
// F: fused DHT (mma) + channel mix (scalar) + trailing transforms (mma).
// One block per (b, blk, x); 256 threads = 8 warps.
// ---------------------------------------------------------------------------
__global__ __launch_bounds__(256) void f_fused(const float* __restrict__ xin,
                                               const float* __restrict__ w1,
                                               const float* __restrict__ w2,
                                               float* __restrict__ out) {
    __shared__ float xs[32 * 260];   // [i][k], pitch 260 (==4 mod 32: frag-LDS conflict-free)
    __shared__ float As[32 * 36];    // [i][y], pitch 36
    __shared__ float rst[32 * 36];   // [o][y], pitch 36 (natural for phase-2 A-frags)

    int t    = threadIdx.x;
    int lane = t & 31, warp = t >> 5;
    int g    = lane >> 2, c = lane & 3;
    int bid  = blockIdx.x;
    int x    = bid & 31;
    int blk  = (bid >> 5) & 1;
    int b    = bid >> 6;
    int row  = blk ? (224 + x) : x;
    const float* w = blk ? w2 : w1;

    // ---- stage x rows into xs (coalesced) ----
    const float4* xb4 = (const float4*)(xin + (((size_t)b * 32) * S + row) * S);
#pragma unroll
    for (int n = t; n < 2048; n += 256) {
        int i = n >> 6, kc = n & 63;
        ((float4*)(xs + i * 260))[kc] = xb4[(size_t)i * (S * S / 4) + kc];
    }
    __syncthreads();

    // ---- phase A: A = X(32i x 256k) @ B(256k x 32y) via mma, 3xTF32 ----
    {
        int mt = warp >> 2, nt = warp & 3;     // warp -> (M-tile, N-tile)
        const float* xr0 = xs + (16 * mt + g) * 260;       // row g
        const float* xr1 = xr0 + 8 * 260;                  // row g+8
        float d0 = 0.f, d1 = 0.f, d2 = 0.f, d3 = 0.f;
        const float4* PA = (const float4*)g_T.PA + nt * 32 + lane;
#pragma unroll 8
        for (int ks = 0; ks < 32; ks++) {
            float f0 = xr0[8 * ks + c];
            float f1 = xr1[8 * ks + c];
            float f2 = xr0[8 * ks + c + 4];
            float f3 = xr1[8 * ks + c + 4];
            uint32_t a0h = cvt_tf32(f0), a1h = cvt_tf32(f1);
            uint32_t a2h = cvt_tf32(f2), a3h = cvt_tf32(f3);
            uint32_t a0l = cvt_tf32(f0 - __uint_as_float(a0h));
            uint32_t a1l = cvt_tf32(f1 - __uint_as_float(a1h));
            uint32_t a2l = cvt_tf32(f2 - __uint_as_float(a2h));
            uint32_t a3l = cvt_tf32(f3 - __uint_as_float(a3h));
            float4 bf = __ldg(PA + ks * 128);
            uint32_t b0h = __float_as_uint(bf.x), b1h = __float_as_uint(bf.y);
            uint32_t b0l = __float_as_uint(bf.z), b1l = __float_as_uint(bf.w);
            MMA_TF32(d0, d1, d2, d3, a0h, a1h, a2h, a3h, b0h, b1h);
            MMA_TF32(d0, d1, d2, d3, a0l, a1l, a2l, a3l, b0h, b1h);
            MMA_TF32(d0, d1, d2, d3, a0h, a1h, a2h, a3h, b0l, b1l);
        }
        int i0 = 16 * mt + g, y0 = 8 * nt + 2 * c;
        *(float2*)&As[i0 * 36 + y0]       = make_float2(d0, d1);
        *(float2*)&As[(i0 + 8) * 36 + y0] = make_float2(d2, d3);
    }

    // ---- zero-fill dead rows [32,224): stores drain during barrier ----
    {
        int img = bid >> 1, half = bid & 1;
        float4* o4 = (float4*)out + (size_t)img * 16384 + 2048 + half * 6144 + t;
#pragma unroll
        for (int j = 0; j < 24; j++) o4[j * 256] = make_float4(0.f, 0.f, 0.f, 0.f);
    }
    __syncthreads();

    // ---- phase 1: channel mix (scalar). thread (yg = t&7, o = t>>3) ----
    {
        int yg = t & 7, o = t >> 3;
        float4 acc = make_float4(0.f, 0.f, 0.f, 0.f);
        const float4* wp = (const float4*)(w + (size_t)o * 1024 + x * 32 + 4 * yg);
        const float4* ap = (const float4*)(As + 4 * yg);
#pragma unroll 8
        for (int i = 0; i < 32; i++) {
            float4 wv = __ldg(&wp[(size_t)i * 8192]);
            float4 av = ap[i * 9];
            acc.x += av.x * wv.x;
            acc.y += av.y * wv.y;
            acc.z += av.z * wv.z;
            acc.w += av.w * wv.w;
        }
        *(float4*)&rst[o * 36 + 4 * yg] = acc;    // natural [o][y]
    }
    __syncthreads();

    // ---- phase 2: out = R(32o x 32y) @ Mm(32y x 256k) via mma, 3xTF32 ----
    {
        int mt = warp & 1, ntg = warp >> 1;       // warp -> (M-tile, 8 N-tiles)
        int r0 = 16 * mt + g;
        uint32_t Ah[4][4], Al[4][4];
#pragma unroll
        for (int ks = 0; ks < 4; ks++) {
            float f0 = rst[r0 * 36 + 8 * ks + c];
            float f1 = rst[(r0 + 8) * 36 + 8 * ks + c];
            float f2 = rst[r0 * 36 + 8 * ks + c + 4];
            float f3 = rst[(r0 + 8) * 36 + 8 * ks + c + 4];
            Ah[ks][0] = cvt_tf32(f0); Al[ks][0] = cvt_tf32(f0 - __uint_as_float(Ah[ks][0]));
            Ah[ks][1] = cvt_tf32(f1); Al[ks][1] = cvt_tf32(f1 - __uint_as_float(Ah[ks][1]));
            Ah[ks][2] = cvt_tf32(f2); Al[ks][2] = cvt_tf32(f2 - __uint_as_float(Ah[ks][2]));
            Ah[ks][3] = cvt_tf32(f3); Al[ks][3] = cvt_tf32(f3 - __uint_as_float(Ah[ks][3]));
        }
#pragma unroll
        for (int j = 0; j < 8; j++) {
            int nt = ntg * 8 + j;
            float d0 = 0.f, d1 = 0.f, d2 = 0.f, d3 = 0.f;
            const float4* PM = (const float4*)g_T.PM + nt * 32 + lane;
#pragma unroll
            for (int ks = 0; ks < 4; ks++) {
                float4 bf = __ldg(PM + ks * 1024);
                uint32_t b0h = __float_as_uint(bf.x), b1h = __float_as_uint(bf.y);
                uint32_t b0l = __float_as_uint(bf.z), b1l = __float_as_uint(bf.w);
                MMA_TF32(d0, d1, d2, d3, Ah[ks][0], Ah[ks][1], Ah[ks][2], Ah[ks][3], b0h, b1h);
                MMA_TF32(d0, d1, d2, d3, Al[ks][0], Al[ks][1], Al[ks][2], Al[ks][3], b0h, b1h);
                MMA_TF32(d0, d1, d2, d3, Ah[ks][0], Ah[ks][1], Ah[ks][2], Ah[ks][3], b0l, b1l);
            }
            float* op = out + (((size_t)(b * 32 + r0)) * S + row) * S + 8 * nt + 2 * c;
            *(float2*)op = make_float2(d0, d1);
            *(float2*)(op + (size_t)8 * S * S) = make_float2(d2, d3);
        }
    }
}

// ---------------------------------------------------------------------------
extern "C" void kernel_launch(void* const* d_in, const int* in_sizes, int n_in,
                              void* d_out, int out_size) {
    const float* x  = (const float*)d_in[0];
    const float* w1 = (const float*)d_in[1];
    const float* w2 = (const float*)d_in[2];
    float* out = (float*)d_out;

    f_fused<<<NB * 2 * 32, 256>>>(x, w1, w2, out);
}

// round 15
// speedup vs baseline: 1.6335x; 1.0503x over previous
#include <cuda_runtime.h>
#include <cstdint>

// SpectralConv2d via DHT — fused kernel; phases A and 2 on tensor cores
// (m16n8k8 tf32, 3xTF32). R15: 3 independent accumulator chains in phase A,
// raw-bit tf32 lo operands; NO min-blocks launch_bounds pin (R13/R14 suspect).

#define NB 8
#define S  256

// ---------------------------------------------------------------------------
// Compile-time trig + tf32 fragment tables.
// ---------------------------------------------------------------------------
constexpr double CPI = 3.14159265358979323846264338327950288;

constexpr double tpoly_cos(double x) {
    double x2 = x * x, term = 1.0, sum = 1.0;
    for (int n = 1; n <= 12; n++) { term *= -x2 / ((2.0*n - 1) * (2.0*n)); sum += term; }
    return sum;
}
constexpr double tpoly_sin(double x) {
    double x2 = x * x, term = x, sum = x;
    for (int n = 1; n <= 12; n++) { term *= -x2 / ((2.0*n) * (2.0*n + 1)); sum += term; }
    return sum;
}
constexpr double cos256(int m) {
    m &= 255; int s = 1;
    if (m > 128) m = 256 - m;
    if (m > 64) { m = 128 - m; s = -1; }
    return s * tpoly_cos((CPI * m) / 128.0);
}
constexpr double sin256(int m) {
    m &= 255; int s = 1;
    if (m > 128) { m = 256 - m; s = -1; }
    if (m > 64) { m = 128 - m; }
    return s * tpoly_sin((CPI * m) / 128.0);
}
constexpr double casd(int m) { return cos256(m) + sin256(m); }

constexpr float tf_hi(double v) {
    float f = (float)v;
    unsigned u = __builtin_bit_cast(unsigned, f);
    u &= 0xFFFFE000u;
    return __builtin_bit_cast(float, u);
}
constexpr float tf_lo(double v) {
    float h = tf_hi(v);
    float l = (float)(v - (double)h);
    unsigned u = __builtin_bit_cast(unsigned, l);
    u &= 0xFFFFE000u;
    return __builtin_bit_cast(float, u);
}

struct alignas(16) F4 { float x, y, z, w; };

// PA[(ks*4+nt)*32+lane]: B-frag for phase A  (B is 256k x 32y, K-dim = k)
//   lane: c = lane&3, g = lane>>2; {b0_hi, b1_hi, b0_lo, b1_lo}
// PM[(ks*32+nt)*32+lane]: same packing for Mm (32y x 256k, K-dim = y)
struct Tables {
    F4 PA[32 * 4 * 32];
    F4 PM[4 * 32 * 32];
};

constexpr Tables make_tables() {
    Tables t{};
    double cas[256] = {};
    for (int m = 0; m < 256; m++) cas[m] = casd(m);
    for (int ks = 0; ks < 32; ks++)
        for (int nt = 0; nt < 4; nt++)
            for (int lane = 0; lane < 32; lane++) {
                int c = lane & 3, g = lane >> 2;
                int k0 = 8 * ks + c, k1 = k0 + 4, y = 8 * nt + g;
                double b0 = cas[(k0 * y) & 255], b1 = cas[(k1 * y) & 255];
                t.PA[(ks * 4 + nt) * 32 + lane] =
                    F4{tf_hi(b0), tf_hi(b1), tf_lo(b0), tf_lo(b1)};
            }
    for (int ks = 0; ks < 4; ks++)
        for (int nt = 0; nt < 32; nt++)
            for (int lane = 0; lane < 32; lane++) {
                int c = lane & 3, g = lane >> 2;
                int y0 = 8 * ks + c, y1 = y0 + 4, k = 8 * nt + g;
                double m0 = 0.0, m1 = 0.0;
                for (int j = 0; j < 32; j++) {
                    double cj = cas[(j * k) & 255];
                    m0 += cas[(8 * ((y0 * j) & 31)) & 255] * cj;
                    m1 += cas[(8 * ((y1 * j) & 31)) & 255] * cj;
                }
                m0 *= 0x1p-42; m1 *= 0x1p-42;
                t.PM[(ks * 32 + nt) * 32 + lane] =
                    F4{tf_hi(m0), tf_hi(m1), tf_lo(m0), tf_lo(m1)};
            }
    return t;
}

__device__ const Tables g_T = make_tables();

// ---------------------------------------------------------------------------
__device__ __forceinline__ uint32_t cvt_tf32(float f) {
    uint32_t r; asm("cvt.rna.tf32.f32 %0, %1;" : "=r"(r) : "f"(f)); return r;
}
#define MMA_TF32(d0,d1,d2,d3,a0,a1,a2,a3,b0,b1)                             \
    asm("mma.sync.aligned.m16n8k8.row.col.f32.tf32.tf32.f32 "               \
        "{%0,%1,%2,%3}, {%4,%5,%6,%7}, {%8,%9}, {%0,%1,%2,%3};"             \
        : "+f"(d0), "+f"(d1), "+f"(d2), "+f"(d3)                            \
        : "r"(a0), "r"(a1), "r"(a2), "r"(a3), "r"(b0), "r"(b1))

// ---------------------------------------------------------------------------
// F: fused DHT (mma) + channel mix (scalar) + trailing transforms (mma).
// One block per (b, blk, x); 256 threads = 8 warps.
// ---------------------------------------------------------------------------
__global__ __launch_bounds__(256) void f_fused(const float* __restrict__ xin,
                                               const float* __restrict__ w1,
                                               const float* __restrict__ w2,
                                               float* __restrict__ out) {
    __shared__ float xs[32 * 260];   // [i][k], pitch 260 (frag-LDS conflict-free)
    __shared__ float As[32 * 36];    // [i][y], pitch 36
    __shared__ float rst[32 * 36];   // [o][y], pitch 36

    int t    = threadIdx.x;
    int lane = t & 31, warp = t >> 5;
    int g    = lane >> 2, c = lane & 3;
    int bid  = blockIdx.x;
    int x    = bid & 31;
    int blk  = (bid >> 5) & 1;
    int b    = bid >> 6;
    int row  = blk ? (224 + x) : x;
    const float* w = blk ? w2 : w1;

    // ---- stage x rows into xs (coalesced) ----
    const float4* xb4 = (const float4*)(xin + (((size_t)b * 32) * S + row) * S);
#pragma unroll
    for (int n = t; n < 2048; n += 256) {
        int i = n >> 6, kc = n & 63;
        ((float4*)(xs + i * 260))[kc] = xb4[(size_t)i * (S * S / 4) + kc];
    }
    __syncthreads();

    // ---- phase A: A = X(32i x 256k) @ B(256k x 32y); 3 independent chains ----
    {
        int mt = warp >> 2, nt = warp & 3;
        const float* xr0 = xs + (16 * mt + g) * 260;
        const float* xr1 = xr0 + 8 * 260;
        float hh0=0.f,hh1=0.f,hh2=0.f,hh3=0.f;   // A_hi * B_hi
        float lh0=0.f,lh1=0.f,lh2=0.f,lh3=0.f;   // A_lo * B_hi
        float hl0=0.f,hl1=0.f,hl2=0.f,hl3=0.f;   // A_hi * B_lo
        const float4* PA = (const float4*)g_T.PA + nt * 32 + lane;
#pragma unroll 8
        for (int ks = 0; ks < 32; ks++) {
            float f0 = xr0[8 * ks + c];
            float f1 = xr1[8 * ks + c];
            float f2 = xr0[8 * ks + c + 4];
            float f3 = xr1[8 * ks + c + 4];
            uint32_t a0h = cvt_tf32(f0), a1h = cvt_tf32(f1);
            uint32_t a2h = cvt_tf32(f2), a3h = cvt_tf32(f3);
            // lo = raw fp32 bits of (x - hi): HW truncates to tf32; residual ~2^-22
            uint32_t a0l = __float_as_uint(f0 - __uint_as_float(a0h));
            uint32_t a1l = __float_as_uint(f1 - __uint_as_float(a1h));
            uint32_t a2l = __float_as_uint(f2 - __uint_as_float(a2h));
            uint32_t a3l = __float_as_uint(f3 - __uint_as_float(a3h));
            float4 bf = __ldg(PA + ks * 128);
            uint32_t b0h = __float_as_uint(bf.x), b1h = __float_as_uint(bf.y);
            uint32_t b0l = __float_as_uint(bf.z), b1l = __float_as_uint(bf.w);
            MMA_TF32(hh0, hh1, hh2, hh3, a0h, a1h, a2h, a3h, b0h, b1h);
            MMA_TF32(lh0, lh1, lh2, lh3, a0l, a1l, a2l, a3l, b0h, b1h);
            MMA_TF32(hl0, hl1, hl2, hl3, a0h, a1h, a2h, a3h, b0l, b1l);
        }
        float d0 = (hh0 + lh0) + hl0;
        float d1 = (hh1 + lh1) + hl1;
        float d2 = (hh2 + lh2) + hl2;
        float d3 = (hh3 + lh3) + hl3;
        int i0 = 16 * mt + g, y0 = 8 * nt + 2 * c;
        *(float2*)&As[i0 * 36 + y0]       = make_float2(d0, d1);
        *(float2*)&As[(i0 + 8) * 36 + y0] = make_float2(d2, d3);
    }

    // ---- zero-fill dead rows [32,224): stores drain during barrier ----
    {
        int img = bid >> 1, half = bid & 1;
        float4* o4 = (float4*)out + (size_t)img * 16384 + 2048 + half * 6144 + t;
#pragma unroll
        for (int j = 0; j < 24; j++) o4[j * 256] = make_float4(0.f, 0.f, 0.f, 0.f);
    }
    __syncthreads();

    // ---- phase 1: channel mix (scalar). thread (yg = t&7, o = t>>3) ----
    {
        int yg = t & 7, o = t >> 3;
        float4 acc = make_float4(0.f, 0.f, 0.f, 0.f);
        const float4* wp = (const float4*)(w + (size_t)o * 1024 + x * 32 + 4 * yg);
        const float4* ap = (const float4*)(As + 4 * yg);
#pragma unroll 8
        for (int i = 0; i < 32; i++) {
            float4 wv = __ldg(&wp[(size_t)i * 8192]);
            float4 av = ap[i * 9];
            acc.x += av.x * wv.x;
            acc.y += av.y * wv.y;
            acc.z += av.z * wv.z;
            acc.w += av.w * wv.w;
        }
        *(float4*)&rst[o * 36 + 4 * yg] = acc;    // natural [o][y]
    }
    __syncthreads();

    // ---- phase 2: out = R(32o x 32y) @ Mm(32y x 256k) via mma, 3xTF32 ----
    {
        int mt = warp & 1, ntg = warp >> 1;
        int r0 = 16 * mt + g;
        uint32_t Ah[4][4], Al[4][4];
#pragma unroll
        for (int ks = 0; ks < 4; ks++) {
            float f0 = rst[r0 * 36 + 8 * ks + c];
            float f1 = rst[(r0 + 8) * 36 + 8 * ks + c];
            float f2 = rst[r0 * 36 + 8 * ks + c + 4];
            float f3 = rst[(r0 + 8) * 36 + 8 * ks + c + 4];
            Ah[ks][0] = cvt_tf32(f0); Al[ks][0] = __float_as_uint(f0 - __uint_as_float(Ah[ks][0]));
            Ah[ks][1] = cvt_tf32(f1); Al[ks][1] = __float_as_uint(f1 - __uint_as_float(Ah[ks][1]));
            Ah[ks][2] = cvt_tf32(f2); Al[ks][2] = __float_as_uint(f2 - __uint_as_float(Ah[ks][2]));
            Ah[ks][3] = cvt_tf32(f3); Al[ks][3] = __float_as_uint(f3 - __uint_as_float(Ah[ks][3]));
        }
#pragma unroll
        for (int j = 0; j < 8; j++) {
            int nt = ntg * 8 + j;
            float d0 = 0.f, d1 = 0.f, d2 = 0.f, d3 = 0.f;
            const float4* PM = (const float4*)g_T.PM + nt * 32 + lane;
#pragma unroll
            for (int ks = 0; ks < 4; ks++) {
                float4 bf = __ldg(PM + ks * 1024);
                uint32_t b0h = __float_as_uint(bf.x), b1h = __float_as_uint(bf.y);
                uint32_t b0l = __float_as_uint(bf.z), b1l = __float_as_uint(bf.w);
                MMA_TF32(d0, d1, d2, d3, Ah[ks][0], Ah[ks][1], Ah[ks][2], Ah[ks][3], b0h, b1h);
                MMA_TF32(d0, d1, d2, d3, Al[ks][0], Al[ks][1], Al[ks][2], Al[ks][3], b0h, b1h);
                MMA_TF32(d0, d1, d2, d3, Ah[ks][0], Ah[ks][1], Ah[ks][2], Ah[ks][3], b0l, b1l);
            }
            float* op = out + (((size_t)(b * 32 + r0)) * S + row) * S + 8 * nt + 2 * c;
            *(float2*)op = make_float2(d0, d1);
            *(float2*)(op + (size_t)8 * S * S) = make_float2(d2, d3);
        }
    }
}

// ---------------------------------------------------------------------------
extern "C" void kernel_launch(void* const* d_in, const int* in_sizes, int n_in,
                              void* d_out, int out_size) {
    const float* x  = (const float*)d_in[0];
    const float* w1 = (const float*)d_in[1];
    const float* w2 = (const float*)d_in[2];
    float* out = (float*)d_out;

    f_fused<<<NB * 2 * 32, 256>>>(x, w1, w2, out);
}